// round 5
// baseline (speedup 1.0000x reference)
#include <cuda_runtime.h>
#include <math.h>
#include <stdint.h>

// ---------------------------------------------------------------------------
// GAT on GB300, round 4:
//  stream A: h = x@W via tf32 mma.sync (m16n8k8), att dots fused in epilogue
//  stream B: per-dst edge linked list via atomicExch (replaces CSR build)
//  join:     warp-per-node single-pass softmax aggregate + ELU
// ---------------------------------------------------------------------------

#define MAXN 100000
#define MAXE 1600000
#define NEG_SLOPE 0.2f

__device__ float g_h[MAXN * 128];         // 51.2 MB
__device__ float g_asrc[MAXN * 4];
__device__ float g_adst[MAXN * 4];
__device__ int   g_head[MAXN];            // -1 terminated list heads
__device__ int   g_next[MAXE];            // list links

// ---------------------------------------------------------------------------
__device__ __forceinline__ float tf32r(float v) {
    uint32_t o;
    asm("cvt.rna.tf32.f32 %0, %1;" : "=r"(o) : "f"(v));
    return __uint_as_float(o);
}

__device__ __forceinline__ void mma_tf32(float c[4],
                                         uint32_t a0, uint32_t a1,
                                         uint32_t a2, uint32_t a3,
                                         uint32_t b0, uint32_t b1) {
    asm volatile(
        "mma.sync.aligned.m16n8k8.row.col.f32.tf32.tf32.f32 "
        "{%0,%1,%2,%3}, {%4,%5,%6,%7}, {%8,%9}, {%0,%1,%2,%3};\n"
        : "+f"(c[0]), "+f"(c[1]), "+f"(c[2]), "+f"(c[3])
        : "r"(a0), "r"(a1), "r"(a2), "r"(a3), "r"(b0), "r"(b1));
}

// ---------------------------------------------------------------------------
// GEMM + fused attention dots. 256 thr / 64 rows per block.
// ---------------------------------------------------------------------------
__global__ void gemm_att_kernel(const float* __restrict__ x,
                                const float* __restrict__ W,
                                const float* __restrict__ att_src,
                                const float* __restrict__ att_dst,
                                float* __restrict__ h,
                                float* __restrict__ asrc,
                                float* __restrict__ adst, int N)
{
    extern __shared__ float sm[];
    float* xs    = sm;                  // 64*132
    float* wt    = sm + 64 * 132;       // 128*132 (W^T: wt[n][k])
    float* attsm = wt + 128 * 132;      // [0:128) att_src, [128:256) att_dst

    const int tid  = threadIdx.x;
    const int row0 = blockIdx.x * 64;

    if (tid < 256)
        attsm[tid] = (tid < 128) ? att_src[tid] : att_dst[tid - 128];

    for (int i = tid; i < 64 * 128; i += 256) {
        int r = i >> 7, k = i & 127;
        int grow = row0 + r;
        float v = (grow < N) ? x[grow * 128 + k] : 0.0f;
        xs[r * 132 + k] = tf32r(v);
    }
    for (int i = tid; i < 128 * 128; i += 256) {
        int k = i >> 7, n = i & 127;
        wt[n * 132 + k] = tf32r(W[i]);
    }
    __syncthreads();

    const int warp = tid >> 5, lane = tid & 31;
    const int mt = warp & 3;       // rows mt*16 .. +16
    const int nh = warp >> 2;      // cols nh*64 .. +64
    const int g = lane >> 2, t = lane & 3;

    float acc[8][4];
    #pragma unroll
    for (int i = 0; i < 8; ++i)
        #pragma unroll
        for (int j = 0; j < 4; ++j) acc[i][j] = 0.0f;

    const float* xA = xs + (mt * 16) * 132;

    #pragma unroll
    for (int k0 = 0; k0 < 128; k0 += 8) {
        uint32_t a0 = __float_as_uint(xA[g * 132 + k0 + t]);
        uint32_t a1 = __float_as_uint(xA[(g + 8) * 132 + k0 + t]);
        uint32_t a2 = __float_as_uint(xA[g * 132 + k0 + t + 4]);
        uint32_t a3 = __float_as_uint(xA[(g + 8) * 132 + k0 + t + 4]);
        #pragma unroll
        for (int nt = 0; nt < 8; ++nt) {
            int n = nh * 64 + nt * 8 + g;
            uint32_t b0 = __float_as_uint(wt[n * 132 + k0 + t]);
            uint32_t b1 = __float_as_uint(wt[n * 132 + k0 + t + 4]);
            mma_tf32(acc[nt], a0, a1, a2, a3, b0, b1);
        }
    }

    const int row_a = row0 + mt * 16 + g;
    const int row_b = row_a + 8;

    float ps[2][2] = {{0, 0}, {0, 0}};
    float pd[2][2] = {{0, 0}, {0, 0}};

    #pragma unroll
    for (int nt = 0; nt < 8; ++nt) {
        int col = nh * 64 + nt * 8 + 2 * t;
        int hl = nt >> 2;
        float as0 = attsm[col],       as1 = attsm[col + 1];
        float ad0 = attsm[128 + col], ad1 = attsm[128 + col + 1];
        ps[0][hl] += acc[nt][0] * as0 + acc[nt][1] * as1;
        ps[1][hl] += acc[nt][2] * as0 + acc[nt][3] * as1;
        pd[0][hl] += acc[nt][0] * ad0 + acc[nt][1] * ad1;
        pd[1][hl] += acc[nt][2] * ad0 + acc[nt][3] * ad1;
        if (row_a < N)
            *(float2*)&h[row_a * 128 + col] = make_float2(acc[nt][0], acc[nt][1]);
        if (row_b < N)
            *(float2*)&h[row_b * 128 + col] = make_float2(acc[nt][2], acc[nt][3]);
    }

    #pragma unroll
    for (int r = 0; r < 2; ++r)
        #pragma unroll
        for (int c = 0; c < 2; ++c) {
            ps[r][c] += __shfl_xor_sync(0xffffffffu, ps[r][c], 1);
            ps[r][c] += __shfl_xor_sync(0xffffffffu, ps[r][c], 2);
            pd[r][c] += __shfl_xor_sync(0xffffffffu, pd[r][c], 1);
            pd[r][c] += __shfl_xor_sync(0xffffffffu, pd[r][c], 2);
        }

    if (t == 0) {
        int h0 = nh * 2, h1 = nh * 2 + 1;
        if (row_a < N) {
            asrc[row_a * 4 + h0] = ps[0][0];
            asrc[row_a * 4 + h1] = ps[0][1];
            adst[row_a * 4 + h0] = pd[0][0];
            adst[row_a * 4 + h1] = pd[0][1];
        }
        if (row_b < N) {
            asrc[row_b * 4 + h0] = ps[1][0];
            asrc[row_b * 4 + h1] = ps[1][1];
            adst[row_b * 4 + h0] = pd[1][0];
            adst[row_b * 4 + h1] = pd[1][1];
        }
    }
}

// ---------------------------------------------------------------------------
// Per-dst linked list: next[e] = atomicExch(&head[dst[e]], e)
// ---------------------------------------------------------------------------
__global__ void link_kernel(const int* __restrict__ ei, int E)
{
    int t = blockIdx.x * blockDim.x + threadIdx.x;
    if (t >= E) return;
    int dst = ei[E + t];
    g_next[t] = atomicExch(&g_head[dst], t);
}

// ---------------------------------------------------------------------------
// Aggregate: warp per node, walks linked list, single-pass softmax, ELU.
// Prefetches next link + next src one hop ahead.
// ---------------------------------------------------------------------------
__device__ __forceinline__ float leaky(float x) {
    return x > 0.0f ? x : NEG_SLOPE * x;
}

__global__ void aggregate_kernel(const float* __restrict__ h,
                                 const float* __restrict__ asrc,
                                 const float* __restrict__ adst,
                                 const float* __restrict__ bias,
                                 const int* __restrict__ ei,
                                 float* __restrict__ out, int N)
{
    int gtid = blockIdx.x * blockDim.x + threadIdx.x;
    int n = gtid >> 5;
    int lane = gtid & 31;
    if (n >= N) return;

    const int myhead = lane >> 3;
    const float admy = adst[n * 4 + myhead];

    // self loop
    float w = __expf(leaky(asrc[n * 4 + myhead] + admy));
    float4 hv = *(const float4*)&h[n * 128 + lane * 4];
    float a0 = w * hv.x, a1 = w * hv.y, a2 = w * hv.z, a3 = w * hv.w;
    float den = ((lane & 7) == 0) ? w : 0.0f;

    int e = g_head[n];
    if (e >= 0) {
        int s = ei[e];
        while (true) {
            int en = g_next[e];
            int sn = (en >= 0) ? ei[en] : 0;        // prefetch next src
            float asv = asrc[s * 4 + myhead];
            float4 v = *(const float4*)&h[s * 128 + lane * 4];
            float we = __expf(leaky(asv + admy));
            a0 += we * v.x; a1 += we * v.y; a2 += we * v.z; a3 += we * v.w;
            if ((lane & 7) == 0) den += we;
            if (en < 0) break;
            e = en; s = sn;
        }
    }

    float dtot = __shfl_sync(0xffffffffu, den, myhead * 8);
    float inv = 1.0f / (dtot + 1e-16f);

    float4 b4 = *(const float4*)&bias[lane * 4];
    float o0 = a0 * inv + b4.x;
    float o1 = a1 * inv + b4.y;
    float o2 = a2 * inv + b4.z;
    float o3 = a3 * inv + b4.w;
    o0 = o0 > 0.0f ? o0 : (__expf(o0) - 1.0f);
    o1 = o1 > 0.0f ? o1 : (__expf(o1) - 1.0f);
    o2 = o2 > 0.0f ? o2 : (__expf(o2) - 1.0f);
    o3 = o3 > 0.0f ? o3 : (__expf(o3) - 1.0f);
    *(float4*)&out[n * 128 + lane * 4] = make_float4(o0, o1, o2, o3);
}

// ---------------------------------------------------------------------------
extern "C" void kernel_launch(void* const* d_in, const int* in_sizes, int n_in,
                              void* d_out, int out_size)
{
    const float* x       = (const float*)d_in[0];
    const int*   ei      = (const int*)d_in[1];
    const float* W       = (const float*)d_in[2];
    const float* att_src = (const float*)d_in[3];
    const float* att_dst = (const float*)d_in[4];
    const float* bias    = (const float*)d_in[5];
    float*       out     = (float*)d_out;

    const int N = in_sizes[0] / 128;
    const int E = in_sizes[1] / 2;

    float *h_p, *asrc_p, *adst_p;
    int *head_p;
    cudaGetSymbolAddress((void**)&h_p,    g_h);
    cudaGetSymbolAddress((void**)&asrc_p, g_asrc);
    cudaGetSymbolAddress((void**)&adst_p, g_adst);
    cudaGetSymbolAddress((void**)&head_p, g_head);

    // lazy-init side stream + fork/join events (host objects only; no device mem)
    static cudaStream_t sB = nullptr;
    static cudaEvent_t evFork = nullptr, evJoin = nullptr;
    if (!sB) {
        cudaStreamCreate(&sB);
        cudaEventCreateWithFlags(&evFork, cudaEventDisableTiming);
        cudaEventCreateWithFlags(&evJoin, cudaEventDisableTiming);
        cudaFuncSetAttribute(gemm_att_kernel,
                             cudaFuncAttributeMaxDynamicSharedMemorySize, 102400);
    }

    // fork: edge-list build on sB, GEMM on main stream
    cudaEventRecord(evFork, 0);
    cudaStreamWaitEvent(sB, evFork, 0);

    cudaMemsetAsync(head_p, 0xFF, N * sizeof(int), sB);   // head = -1
    link_kernel<<<(E + 255) / 256, 256, 0, sB>>>(ei, E);
    cudaEventRecord(evJoin, sB);

    gemm_att_kernel<<<(N + 63) / 64, 256, 102400>>>(x, W, att_src, att_dst,
                                                    h_p, asrc_p, adst_p, N);

    // join, then aggregate
    cudaStreamWaitEvent(0, evJoin, 0);
    aggregate_kernel<<<(N * 32 + 255) / 256, 256>>>(h_p, asrc_p, adst_p,
                                                    bias, ei, out, N);
}

// round 8
// speedup vs baseline: 1.0856x; 1.0856x over previous
#include <cuda_runtime.h>
#include <math.h>
#include <stdint.h>

// ---------------------------------------------------------------------------
// GAT on GB300, round 5:
//  stream A: h = x@W via tf32 mma.sync, att dots fused in epilogue
//  stream B: CSR-by-dst build (count -> scan -> fill)   [overlapped with A]
//  join:     warp-per-node single-pass softmax aggregate + ELU (CSR walk)
// ---------------------------------------------------------------------------

#define MAXN 100000
#define MAXE 1600000
#define NEG_SLOPE 0.2f

__device__ float g_h[MAXN * 128];         // 51.2 MB
__device__ float g_asrc[MAXN * 4];
__device__ float g_adst[MAXN * 4];
__device__ int   g_cnt[MAXN];
__device__ int   g_off[MAXN + 1];
__device__ int   g_cur[MAXN];
__device__ int   g_csr[MAXE];
__device__ int   g_bsums[256];

// ---------------------------------------------------------------------------
__device__ __forceinline__ float tf32r(float v) {
    uint32_t o;
    asm("cvt.rna.tf32.f32 %0, %1;" : "=r"(o) : "f"(v));
    return __uint_as_float(o);
}

__device__ __forceinline__ void mma_tf32(float c[4],
                                         uint32_t a0, uint32_t a1,
                                         uint32_t a2, uint32_t a3,
                                         uint32_t b0, uint32_t b1) {
    asm volatile(
        "mma.sync.aligned.m16n8k8.row.col.f32.tf32.tf32.f32 "
        "{%0,%1,%2,%3}, {%4,%5,%6,%7}, {%8,%9}, {%0,%1,%2,%3};\n"
        : "+f"(c[0]), "+f"(c[1]), "+f"(c[2]), "+f"(c[3])
        : "r"(a0), "r"(a1), "r"(a2), "r"(a3), "r"(b0), "r"(b1));
}

// ---------------------------------------------------------------------------
// GEMM + fused attention dots. 256 thr / 64 rows per block.
// ---------------------------------------------------------------------------
__global__ void gemm_att_kernel(const float* __restrict__ x,
                                const float* __restrict__ W,
                                const float* __restrict__ att_src,
                                const float* __restrict__ att_dst,
                                float* __restrict__ h,
                                float* __restrict__ asrc,
                                float* __restrict__ adst, int N)
{
    extern __shared__ float sm[];
    float* xs    = sm;                  // 64*132
    float* wt    = sm + 64 * 132;       // 128*132 (W^T: wt[n][k])
    float* attsm = wt + 128 * 132;      // [0:128) att_src, [128:256) att_dst

    const int tid  = threadIdx.x;
    const int row0 = blockIdx.x * 64;

    if (tid < 256)
        attsm[tid] = (tid < 128) ? att_src[tid] : att_dst[tid - 128];

    for (int i = tid; i < 64 * 128; i += 256) {
        int r = i >> 7, k = i & 127;
        int grow = row0 + r;
        float v = (grow < N) ? x[grow * 128 + k] : 0.0f;
        xs[r * 132 + k] = tf32r(v);
    }
    for (int i = tid; i < 128 * 128; i += 256) {
        int k = i >> 7, n = i & 127;
        wt[n * 132 + k] = tf32r(W[i]);
    }
    __syncthreads();

    const int warp = tid >> 5, lane = tid & 31;
    const int mt = warp & 3;
    const int nh = warp >> 2;
    const int g = lane >> 2, t = lane & 3;

    float acc[8][4];
    #pragma unroll
    for (int i = 0; i < 8; ++i)
        #pragma unroll
        for (int j = 0; j < 4; ++j) acc[i][j] = 0.0f;

    const float* xA = xs + (mt * 16) * 132;

    #pragma unroll
    for (int k0 = 0; k0 < 128; k0 += 8) {
        uint32_t a0 = __float_as_uint(xA[g * 132 + k0 + t]);
        uint32_t a1 = __float_as_uint(xA[(g + 8) * 132 + k0 + t]);
        uint32_t a2 = __float_as_uint(xA[g * 132 + k0 + t + 4]);
        uint32_t a3 = __float_as_uint(xA[(g + 8) * 132 + k0 + t + 4]);
        #pragma unroll
        for (int nt = 0; nt < 8; ++nt) {
            int n = nh * 64 + nt * 8 + g;
            uint32_t b0 = __float_as_uint(wt[n * 132 + k0 + t]);
            uint32_t b1 = __float_as_uint(wt[n * 132 + k0 + t + 4]);
            mma_tf32(acc[nt], a0, a1, a2, a3, b0, b1);
        }
    }

    const int row_a = row0 + mt * 16 + g;
    const int row_b = row_a + 8;

    float ps[2][2] = {{0, 0}, {0, 0}};
    float pd[2][2] = {{0, 0}, {0, 0}};

    #pragma unroll
    for (int nt = 0; nt < 8; ++nt) {
        int col = nh * 64 + nt * 8 + 2 * t;
        int hl = nt >> 2;
        float as0 = attsm[col],       as1 = attsm[col + 1];
        float ad0 = attsm[128 + col], ad1 = attsm[128 + col + 1];
        ps[0][hl] += acc[nt][0] * as0 + acc[nt][1] * as1;
        ps[1][hl] += acc[nt][2] * as0 + acc[nt][3] * as1;
        pd[0][hl] += acc[nt][0] * ad0 + acc[nt][1] * ad1;
        pd[1][hl] += acc[nt][2] * ad0 + acc[nt][3] * ad1;
        if (row_a < N)
            *(float2*)&h[row_a * 128 + col] = make_float2(acc[nt][0], acc[nt][1]);
        if (row_b < N)
            *(float2*)&h[row_b * 128 + col] = make_float2(acc[nt][2], acc[nt][3]);
    }

    #pragma unroll
    for (int r = 0; r < 2; ++r)
        #pragma unroll
        for (int c = 0; c < 2; ++c) {
            ps[r][c] += __shfl_xor_sync(0xffffffffu, ps[r][c], 1);
            ps[r][c] += __shfl_xor_sync(0xffffffffu, ps[r][c], 2);
            pd[r][c] += __shfl_xor_sync(0xffffffffu, pd[r][c], 1);
            pd[r][c] += __shfl_xor_sync(0xffffffffu, pd[r][c], 2);
        }

    if (t == 0) {
        int h0 = nh * 2, h1 = nh * 2 + 1;
        if (row_a < N) {
            asrc[row_a * 4 + h0] = ps[0][0];
            asrc[row_a * 4 + h1] = ps[0][1];
            adst[row_a * 4 + h0] = pd[0][0];
            adst[row_a * 4 + h1] = pd[0][1];
        }
        if (row_b < N) {
            asrc[row_b * 4 + h0] = ps[1][0];
            asrc[row_b * 4 + h1] = ps[1][1];
            adst[row_b * 4 + h0] = pd[1][0];
            adst[row_b * 4 + h1] = pd[1][1];
        }
    }
}

// ---------------------------------------------------------------------------
// CSR build (runs on side stream, overlapped with GEMM)
// ---------------------------------------------------------------------------
__global__ void count_kernel(const int* __restrict__ ei, int E)
{
    int t = blockIdx.x * blockDim.x + threadIdx.x;
    if (t >= E) return;
    atomicAdd(&g_cnt[ei[E + t]], 1);
}

__global__ void scan1_kernel(int N)
{
    __shared__ int sh[1024];
    int tid = threadIdx.x;
    int i = blockIdx.x * 1024 + tid;
    int v = (i < N) ? g_cnt[i] : 0;
    sh[tid] = v;
    __syncthreads();
    #pragma unroll
    for (int off = 1; off < 1024; off <<= 1) {
        int t = (tid >= off) ? sh[tid - off] : 0;
        __syncthreads();
        sh[tid] += t;
        __syncthreads();
    }
    int inc = sh[tid];
    if (i < N) g_off[i] = inc - v;
    if (tid == 1023) g_bsums[blockIdx.x] = inc;
}

__global__ void scan2_kernel(int NB, int N)
{
    __shared__ int sh[128];
    int tid = threadIdx.x;
    int v = (tid < NB) ? g_bsums[tid] : 0;
    sh[tid] = v;
    __syncthreads();
    #pragma unroll
    for (int off = 1; off < 128; off <<= 1) {
        int t = (tid >= off) ? sh[tid - off] : 0;
        __syncthreads();
        sh[tid] += t;
        __syncthreads();
    }
    int inc = sh[tid];
    if (tid < NB) g_bsums[tid] = inc - v;
    if (tid == NB - 1) g_off[N] = inc;
}

__global__ void scan3_kernel(int N)
{
    int i = blockIdx.x * blockDim.x + threadIdx.x;
    if (i >= N) return;
    int o = g_off[i] + g_bsums[i >> 10];
    g_off[i] = o;
    g_cur[i] = o;
}

__global__ void fill_kernel(const int* __restrict__ ei, int E)
{
    int t = blockIdx.x * blockDim.x + threadIdx.x;
    if (t >= E) return;
    int src = ei[t];
    int dst = ei[E + t];
    int pos = atomicAdd(&g_cur[dst], 1);
    g_csr[pos] = src;
}

// ---------------------------------------------------------------------------
// Aggregate: warp per node, CSR walk, single-pass softmax, ELU.
// ---------------------------------------------------------------------------
__device__ __forceinline__ float leaky(float x) {
    return x > 0.0f ? x : NEG_SLOPE * x;
}

__global__ void aggregate_kernel(const float* __restrict__ h,
                                 const float* __restrict__ asrc,
                                 const float* __restrict__ adst,
                                 const float* __restrict__ bias,
                                 float* __restrict__ out, int N)
{
    int gtid = blockIdx.x * blockDim.x + threadIdx.x;
    int n = gtid >> 5;
    int lane = gtid & 31;
    if (n >= N) return;

    const int s0 = g_off[n];
    const int s1 = g_off[n + 1];
    const int myhead = lane >> 3;

    const float admy = adst[n * 4 + myhead];

    // self loop
    float w = __expf(leaky(asrc[n * 4 + myhead] + admy));
    float4 hv = *(const float4*)&h[n * 128 + lane * 4];
    float a0 = w * hv.x, a1 = w * hv.y, a2 = w * hv.z, a3 = w * hv.w;
    float den = ((lane & 7) == 0) ? w : 0.0f;

    int e = s0;
    for (; e + 2 <= s1; e += 2) {
        int sA = g_csr[e];
        int sB = g_csr[e + 1];
        float asA = asrc[sA * 4 + myhead];
        float asB = asrc[sB * 4 + myhead];
        float4 vA = *(const float4*)&h[sA * 128 + lane * 4];
        float4 vB = *(const float4*)&h[sB * 128 + lane * 4];
        float wA = __expf(leaky(asA + admy));
        float wB = __expf(leaky(asB + admy));
        a0 += wA * vA.x; a1 += wA * vA.y; a2 += wA * vA.z; a3 += wA * vA.w;
        a0 += wB * vB.x; a1 += wB * vB.y; a2 += wB * vB.z; a3 += wB * vB.w;
        if ((lane & 7) == 0) den += wA + wB;
    }
    if (e < s1) {
        int s = g_csr[e];
        float asv = asrc[s * 4 + myhead];
        float4 v = *(const float4*)&h[s * 128 + lane * 4];
        float we = __expf(leaky(asv + admy));
        a0 += we * v.x; a1 += we * v.y; a2 += we * v.z; a3 += we * v.w;
        if ((lane & 7) == 0) den += we;
    }

    float dtot = __shfl_sync(0xffffffffu, den, myhead * 8);
    float inv = 1.0f / (dtot + 1e-16f);

    float4 b4 = *(const float4*)&bias[lane * 4];
    float o0 = a0 * inv + b4.x;
    float o1 = a1 * inv + b4.y;
    float o2 = a2 * inv + b4.z;
    float o3 = a3 * inv + b4.w;
    o0 = o0 > 0.0f ? o0 : (__expf(o0) - 1.0f);
    o1 = o1 > 0.0f ? o1 : (__expf(o1) - 1.0f);
    o2 = o2 > 0.0f ? o2 : (__expf(o2) - 1.0f);
    o3 = o3 > 0.0f ? o3 : (__expf(o3) - 1.0f);
    *(float4*)&out[n * 128 + lane * 4] = make_float4(o0, o1, o2, o3);
}

// ---------------------------------------------------------------------------
extern "C" void kernel_launch(void* const* d_in, const int* in_sizes, int n_in,
                              void* d_out, int out_size)
{
    const float* x       = (const float*)d_in[0];
    const int*   ei      = (const int*)d_in[1];
    const float* W       = (const float*)d_in[2];
    const float* att_src = (const float*)d_in[3];
    const float* att_dst = (const float*)d_in[4];
    const float* bias    = (const float*)d_in[5];
    float*       out     = (float*)d_out;

    const int N = in_sizes[0] / 128;
    const int E = in_sizes[1] / 2;

    float *h_p, *asrc_p, *adst_p;
    int *cnt_p;
    cudaGetSymbolAddress((void**)&h_p,    g_h);
    cudaGetSymbolAddress((void**)&asrc_p, g_asrc);
    cudaGetSymbolAddress((void**)&adst_p, g_adst);
    cudaGetSymbolAddress((void**)&cnt_p,  g_cnt);

    // lazy-init side stream + fork/join events (host objects only)
    static cudaStream_t sB = nullptr;
    static cudaEvent_t evFork = nullptr, evJoin = nullptr;
    if (!sB) {
        cudaStreamCreate(&sB);
        cudaEventCreateWithFlags(&evFork, cudaEventDisableTiming);
        cudaEventCreateWithFlags(&evJoin, cudaEventDisableTiming);
        cudaFuncSetAttribute(gemm_att_kernel,
                             cudaFuncAttributeMaxDynamicSharedMemorySize, 102400);
    }

    // fork: CSR build on sB, GEMM on main stream
    cudaEventRecord(evFork, 0);
    cudaStreamWaitEvent(sB, evFork, 0);

    cudaMemsetAsync(cnt_p, 0, N * sizeof(int), sB);
    count_kernel<<<(E + 255) / 256, 256, 0, sB>>>(ei, E);
    int NB = (N + 1023) / 1024;
    scan1_kernel<<<NB, 1024, 0, sB>>>(N);
    scan2_kernel<<<1, 128, 0, sB>>>(NB, N);
    scan3_kernel<<<(N + 255) / 256, 256, 0, sB>>>(N);
    fill_kernel<<<(E + 255) / 256, 256, 0, sB>>>(ei, E);
    cudaEventRecord(evJoin, sB);

    gemm_att_kernel<<<(N + 63) / 64, 256, 102400>>>(x, W, att_src, att_dst,
                                                    h_p, asrc_p, adst_p, N);

    // join, then aggregate
    cudaStreamWaitEvent(0, evJoin, 0);
    aggregate_kernel<<<(N * 32 + 255) / 256, 256>>>(h_p, asrc_p, adst_p,
                                                    bias, out, N);
}